// round 1
// baseline (speedup 1.0000x reference)
#include <cuda_runtime.h>
#include <math_constants.h>

#define NN   50000
#define EE   1600000
#define D    64
#define DE   16
#define ATT_SLOPE 0.2f
#define ACT_SLOPE 0.01f

// ---------------- scratch (device globals; no allocation allowed) -----------
__device__ float g_h [NN * D];   // current layer transformed features
__device__ float g_c1[NN * D];   // layer-1 output (post-activation)
__device__ float g_hs[NN];
__device__ float g_hd[NN];
__device__ float g_l [EE];       // per-edge logits (CSR order)
__device__ int   g_deg[NN];
__device__ int   g_rowptr[NN + 1];
__device__ int   g_cursor[NN];
__device__ int   g_eid[EE];      // CSR -> original edge id

// ---------------- CSR construction ------------------------------------------
__global__ void k_zero_deg() {
    int i = blockIdx.x * blockDim.x + threadIdx.x;
    if (i < NN) g_deg[i] = 0;
}

__global__ void k_hist(const int* __restrict__ dst) {
    int e = blockIdx.x * blockDim.x + threadIdx.x;
    if (e < EE) atomicAdd(&g_deg[dst[e]], 1);
}

// single-block exclusive scan (1024 threads, shuffle-based)
__global__ void k_scan() {
    __shared__ int warp_sums[32];
    __shared__ int s_carry;
    int tid = threadIdx.x, lane = tid & 31, wid = tid >> 5;
    if (tid == 0) s_carry = 0;
    __syncthreads();
    for (int base = 0; base < NN; base += 1024) {
        int i = base + tid;
        int v = (i < NN) ? g_deg[i] : 0;
        int x = v;
        #pragma unroll
        for (int o = 1; o < 32; o <<= 1) {
            int t = __shfl_up_sync(0xffffffffu, x, o);
            if (lane >= o) x += t;
        }
        if (lane == 31) warp_sums[wid] = x;
        __syncthreads();
        if (wid == 0) {
            int ws = warp_sums[lane];
            #pragma unroll
            for (int o = 1; o < 32; o <<= 1) {
                int t = __shfl_up_sync(0xffffffffu, ws, o);
                if (lane >= o) ws += t;
            }
            warp_sums[lane] = ws;
        }
        __syncthreads();
        int warp_off = (wid > 0) ? warp_sums[wid - 1] : 0;
        int incl = x + warp_off + s_carry;
        if (i < NN) {
            g_rowptr[i] = incl - v;
            g_cursor[i] = incl - v;
        }
        __syncthreads();
        if (tid == 1023) s_carry = incl;
        __syncthreads();
    }
    if (threadIdx.x == 0) g_rowptr[NN] = s_carry;
}

__global__ void k_scatter(const int* __restrict__ dst) {
    int e = blockIdx.x * blockDim.x + threadIdx.x;
    if (e < EE) {
        int p = atomicAdd(&g_cursor[dst[e]], 1);
        g_eid[p] = e;
    }
}

// ---------------- feature transform: h = x@W, hs = h.a_s, hd = h.a_d --------
__global__ void k_feat(const float* __restrict__ xin,
                       const float* __restrict__ W,
                       const float* __restrict__ a_s,
                       const float* __restrict__ a_d,
                       int use_c1) {
    __shared__ float sW[D * D];
    __shared__ float sas[D], sad[D];
    __shared__ float sx[8][D];
    const float* __restrict__ x = use_c1 ? g_c1 : xin;
    int tid = threadIdx.x;
    for (int i = tid; i < D * D; i += blockDim.x) sW[i] = W[i];
    if (tid < D) { sas[tid] = a_s[tid]; sad[tid] = a_d[tid]; }
    __syncthreads();
    int warp = tid >> 5, lane = tid & 31;
    int gw = blockIdx.x * 8 + warp;
    int nw = gridDim.x * 8;
    for (int row = gw; row < NN; row += nw) {
        float x0 = x[row * D + lane];
        float x1 = x[row * D + 32 + lane];
        sx[warp][lane]      = x0;
        sx[warp][lane + 32] = x1;
        __syncwarp();
        float h0 = 0.f, h1 = 0.f;
        #pragma unroll
        for (int k = 0; k < D; k++) {
            float xv = sx[warp][k];
            h0 = fmaf(xv, sW[k * D + lane],      h0);
            h1 = fmaf(xv, sW[k * D + lane + 32], h1);
        }
        g_h[row * D + lane]      = h0;
        g_h[row * D + lane + 32] = h1;
        float ps = h0 * sas[lane] + h1 * sas[lane + 32];
        float pd = h0 * sad[lane] + h1 * sad[lane + 32];
        #pragma unroll
        for (int o = 16; o; o >>= 1) {
            ps += __shfl_xor_sync(0xffffffffu, ps, o);
            pd += __shfl_xor_sync(0xffffffffu, pd, o);
        }
        if (lane == 0) { g_hs[row] = ps; g_hd[row] = pd; }
        __syncwarp();
    }
}

// ---------------- fused GAT: logits -> softmax -> weighted max aggregation --
// warp per dst node; lane owns dims {lane, lane+32}
__global__ void k_gat(const int* __restrict__ src,
                      const float* __restrict__ edge_attr,
                      const float* __restrict__ We,
                      const float* __restrict__ ae,
                      const float* __restrict__ bias,
                      float* __restrict__ dout,
                      int to_c1) {
    __shared__ float sWe[DE * D];
    __shared__ float swea[DE];
    __shared__ float sb[D];
    float* __restrict__ out = to_c1 ? g_c1 : dout;
    int tid = threadIdx.x;
    for (int i = tid; i < DE * D; i += blockDim.x) sWe[i] = We[i];
    if (tid < D) sb[tid] = bias[tid];
    __syncthreads();
    if (tid < DE) {
        float acc = 0.f;
        #pragma unroll
        for (int dd = 0; dd < D; dd++) acc = fmaf(sWe[tid * D + dd], ae[dd], acc);
        swea[tid] = acc;
    }
    __syncthreads();

    int warp = tid >> 5, lane = tid & 31;
    int gw = blockIdx.x * (blockDim.x >> 5) + warp;
    int nw = gridDim.x * (blockDim.x >> 5);

    for (int n = gw; n < NN; n += nw) {
        int beg = g_rowptr[n], end = g_rowptr[n + 1];
        float out0, out1;
        if (beg == end) {
            out0 = 0.f; out1 = 0.f;
        } else {
            float hdn = g_hd[n];
            // ---- pass 1: logits + segment max ----
            float mmax = -CUDART_INF_F;
            for (int idx = beg + lane; idx < end; idx += 32) {
                int e = g_eid[idx];
                const float4* ea4 = (const float4*)(edge_attr + (size_t)e * DE);
                float4 A = ea4[0], B = ea4[1], C = ea4[2], Dd = ea4[3];
                float l = g_hs[src[e]] + hdn;
                l = fmaf(A.x, swea[0],  l); l = fmaf(A.y, swea[1],  l);
                l = fmaf(A.z, swea[2],  l); l = fmaf(A.w, swea[3],  l);
                l = fmaf(B.x, swea[4],  l); l = fmaf(B.y, swea[5],  l);
                l = fmaf(B.z, swea[6],  l); l = fmaf(B.w, swea[7],  l);
                l = fmaf(C.x, swea[8],  l); l = fmaf(C.y, swea[9],  l);
                l = fmaf(C.z, swea[10], l); l = fmaf(C.w, swea[11], l);
                l = fmaf(Dd.x, swea[12], l); l = fmaf(Dd.y, swea[13], l);
                l = fmaf(Dd.z, swea[14], l); l = fmaf(Dd.w, swea[15], l);
                l = fmaxf(l, ATT_SLOPE * l);   // leaky_relu(l, 0.2)
                g_l[idx] = l;
                mmax = fmaxf(mmax, l);
            }
            #pragma unroll
            for (int o = 16; o; o >>= 1)
                mmax = fmaxf(mmax, __shfl_xor_sync(0xffffffffu, mmax, o));
            __syncwarp();  // make g_l writes visible across the warp

            // ---- pass 2: p, sum, and max(p * (h[src]+e)) ----
            // att = p/s with s>0 uniform per node, so max distributes: acc/s
            float s = 0.f;
            float a0 = -CUDART_INF_F, a1 = -CUDART_INF_F;
            for (int idx = beg; idx < end; idx++) {
                int e = g_eid[idx];
                float p = __expf(g_l[idx] - mmax);   // arg <= 0
                s += p;
                const float4* ea4 = (const float4*)(edge_attr + (size_t)e * DE);
                float4 A = ea4[0], B = ea4[1], C = ea4[2], Dd = ea4[3];
                float ev[16] = {A.x,A.y,A.z,A.w, B.x,B.y,B.z,B.w,
                                C.x,C.y,C.z,C.w, Dd.x,Dd.y,Dd.z,Dd.w};
                float e0 = 0.f, e1 = 0.f;
                #pragma unroll
                for (int k = 0; k < DE; k++) {
                    e0 = fmaf(ev[k], sWe[k * D + lane],      e0);
                    e1 = fmaf(ev[k], sWe[k * D + lane + 32], e1);
                }
                int sr = src[e];
                float v0 = g_h[sr * D + lane]      + e0;
                float v1 = g_h[sr * D + lane + 32] + e1;
                a0 = fmaxf(a0, p * v0);
                a1 = fmaxf(a1, p * v1);
            }
            float inv = 1.0f / s;     // s >= 1 always (max logit contributes p=1)
            out0 = a0 * inv;
            out1 = a1 * inv;
        }
        out0 += sb[lane];
        out1 += sb[lane + 32];
        out0 = fmaxf(out0, ACT_SLOPE * out0);   // leaky_relu(., 0.01)
        out1 = fmaxf(out1, ACT_SLOPE * out1);
        out[n * D + lane]      = out0;
        out[n * D + lane + 32] = out1;
    }
}

// ---------------- launch -----------------------------------------------------
extern "C" void kernel_launch(void* const* d_in, const int* in_sizes, int n_in,
                              void* d_out, int out_size) {
    const float* X     = (const float*)d_in[0];
    const int*   ei    = (const int*)  d_in[1];
    const float* eattr = (const float*)d_in[2];
    const float* W1  = (const float*)d_in[3];
    const float* We1 = (const float*)d_in[4];
    const float* as1 = (const float*)d_in[5];
    const float* ad1 = (const float*)d_in[6];
    const float* ae1 = (const float*)d_in[7];
    const float* b1  = (const float*)d_in[8];
    const float* W2  = (const float*)d_in[9];
    const float* We2 = (const float*)d_in[10];
    const float* as2 = (const float*)d_in[11];
    const float* ad2 = (const float*)d_in[12];
    const float* ae2 = (const float*)d_in[13];
    const float* b2  = (const float*)d_in[14];

    const int* srcp = ei;
    const int* dstp = ei + EE;
    float* out = (float*)d_out;

    const int EB = (EE + 255) / 256;         // 6250
    const int NB = (NN + 255) / 256;         // 196
    const int GB = (NN + 7) / 8;             // 6250 blocks * 8 warps = 50000

    // CSR build (once per launch, shared by both layers)
    k_zero_deg<<<NB, 256>>>();
    k_hist<<<EB, 256>>>(dstp);
    k_scan<<<1, 1024>>>();
    k_scatter<<<EB, 256>>>(dstp);

    // layer 1
    k_feat<<<GB, 256>>>(X, W1, as1, ad1, /*use_c1=*/0);
    k_gat <<<GB, 256>>>(srcp, eattr, We1, ae1, b1, out, /*to_c1=*/1);

    // layer 2
    k_feat<<<GB, 256>>>(nullptr, W2, as2, ad2, /*use_c1=*/1);
    k_gat <<<GB, 256>>>(srcp, eattr, We2, ae2, b2, out, /*to_c1=*/0);
}

// round 2
// speedup vs baseline: 1.7495x; 1.7495x over previous
#include <cuda_runtime.h>
#include <math_constants.h>

#define NN   50000
#define EE   1600000
#define D    64
#define DE   16
#define ATT_SLOPE 0.2f
#define ACT_SLOPE 0.01f

typedef unsigned long long u64;
union F2U { u64 u; float2 f; };

__device__ __forceinline__ u64 fma2(u64 a, u64 b, u64 c) {
    u64 d; asm("fma.rn.f32x2 %0, %1, %2, %3;" : "=l"(d) : "l"(a), "l"(b), "l"(c));
    return d;
}
__device__ __forceinline__ u64 pack2(float x, float y) {
    F2U t; t.f = make_float2(x, y); return t.u;
}

// ---------------- scratch (device globals; no allocation allowed) -----------
__device__ float2 g_h [NN * 32];   // transformed features, dim pairs (2l,2l+1)
__device__ float2 g_c1[NN * 32];   // layer-1 output
__device__ float  g_hs[NN];
__device__ float  g_hd[NN];
__device__ float  g_l [EE];        // logits, then p, CSR order
__device__ int    g_deg[NN];
__device__ int    g_rowptr[NN + 1];
__device__ int    g_cursor[NN];
__device__ int    g_eid [EE];      // CSR -> original edge id
__device__ int    g_srcc[EE];      // CSR-ordered src node
__device__ int    g_bsum[64];

// ---------------- CSR construction ------------------------------------------
__global__ void k_zero_deg() {
    int i = blockIdx.x * blockDim.x + threadIdx.x;
    if (i < NN) g_deg[i] = 0;
}

__global__ void k_hist(const int* __restrict__ dst) {
    int i = blockIdx.x * blockDim.x + threadIdx.x;
    if (i < EE / 4) {
        int4 v = ((const int4*)dst)[i];
        atomicAdd(&g_deg[v.x], 1);
        atomicAdd(&g_deg[v.y], 1);
        atomicAdd(&g_deg[v.z], 1);
        atomicAdd(&g_deg[v.w], 1);
    }
}

// block-local exclusive scan (1024/block), 49 blocks cover NN
__global__ void k_scan1() {
    __shared__ int wsum[32];
    int tid = threadIdx.x, lane = tid & 31, wid = tid >> 5;
    int i = blockIdx.x * 1024 + tid;
    int v = (i < NN) ? g_deg[i] : 0;
    int x = v;
    #pragma unroll
    for (int o = 1; o < 32; o <<= 1) {
        int t = __shfl_up_sync(0xffffffffu, x, o);
        if (lane >= o) x += t;
    }
    if (lane == 31) wsum[wid] = x;
    __syncthreads();
    if (wid == 0) {
        int w = wsum[lane];
        #pragma unroll
        for (int o = 1; o < 32; o <<= 1) {
            int t = __shfl_up_sync(0xffffffffu, w, o);
            if (lane >= o) w += t;
        }
        wsum[lane] = w;
    }
    __syncthreads();
    int off = wid ? wsum[wid - 1] : 0;
    if (i < NN) g_rowptr[i] = x - v + off;
    if (tid == 1023) g_bsum[blockIdx.x] = x + off;  // block total
}

__global__ void k_scan2() {
    int i = blockIdx.x * blockDim.x + threadIdx.x;
    if (i == 0) g_rowptr[NN] = EE;
    if (i < NN) {
        int b = i >> 10;
        int off = 0;
        for (int j = 0; j < b; j++) off += g_bsum[j];
        int r = g_rowptr[i] + off;
        g_rowptr[i] = r;
        g_cursor[i] = r;
    }
}

__global__ void k_scatter(const int* __restrict__ src, const int* __restrict__ dst) {
    int i = blockIdx.x * blockDim.x + threadIdx.x;
    if (i < EE / 4) {
        int4 dv = ((const int4*)dst)[i];
        int4 sv = ((const int4*)src)[i];
        int e = 4 * i;
        int p;
        p = atomicAdd(&g_cursor[dv.x], 1); g_eid[p] = e + 0; g_srcc[p] = sv.x;
        p = atomicAdd(&g_cursor[dv.y], 1); g_eid[p] = e + 1; g_srcc[p] = sv.y;
        p = atomicAdd(&g_cursor[dv.z], 1); g_eid[p] = e + 2; g_srcc[p] = sv.z;
        p = atomicAdd(&g_cursor[dv.w], 1); g_eid[p] = e + 3; g_srcc[p] = sv.w;
    }
}

// ---------------- feature transform: h = x@W, hs = h.a_s, hd = h.a_d --------
// warp handles 4 rows at a time; lane owns dim pair (2l, 2l+1)
__global__ void __launch_bounds__(256) k_feat(const float* __restrict__ xin,
                                              const float* __restrict__ W,
                                              const float* __restrict__ a_s,
                                              const float* __restrict__ a_d,
                                              int use_c1) {
    __shared__ u64 sW2[D * 32];        // W pairs: sW2[k*32+l] = {W[k][2l], W[k][2l+1]}
    __shared__ float sx[8][4][D];
    __shared__ u64 sas2[32], sad2[32];
    const float* __restrict__ x = use_c1 ? (const float*)g_c1 : xin;
    int tid = threadIdx.x;
    for (int i = tid; i < D * 32; i += 256) sW2[i] = ((const u64*)W)[i];
    if (tid < 32) { sas2[tid] = ((const u64*)a_s)[tid]; sad2[tid] = ((const u64*)a_d)[tid]; }
    __syncthreads();
    int warp = tid >> 5, lane = tid & 31;
    F2U asv; asv.u = sas2[lane];
    F2U adv; adv.u = sad2[lane];
    int gw = blockIdx.x * 8 + warp;
    int nw = gridDim.x * 8;
    for (int r0 = gw * 4; r0 < NN; r0 += nw * 4) {
        #pragma unroll
        for (int r = 0; r < 4; r++) {
            int row = r0 + r;
            sx[warp][r][lane]      = x[row * D + lane];
            sx[warp][r][lane + 32] = x[row * D + lane + 32];
        }
        __syncwarp();
        F2U acc[4];
        #pragma unroll
        for (int r = 0; r < 4; r++) acc[r].u = 0ull;
        #pragma unroll
        for (int k = 0; k < D; k++) {
            u64 wp = sW2[k * 32 + lane];
            #pragma unroll
            for (int r = 0; r < 4; r++) {
                float xv = sx[warp][r][k];
                acc[r].u = fma2(pack2(xv, xv), wp, acc[r].u);
            }
        }
        #pragma unroll
        for (int r = 0; r < 4; r++) {
            int row = r0 + r;
            g_h[row * 32 + lane] = acc[r].f;
            float ps = acc[r].f.x * asv.f.x + acc[r].f.y * asv.f.y;
            float pd = acc[r].f.x * adv.f.x + acc[r].f.y * adv.f.y;
            #pragma unroll
            for (int o = 16; o; o >>= 1) {
                ps += __shfl_xor_sync(0xffffffffu, ps, o);
                pd += __shfl_xor_sync(0xffffffffu, pd, o);
            }
            if (lane == 0) { g_hs[row] = ps; g_hd[row] = pd; }
        }
        __syncwarp();
    }
}

// ---------------- fused GAT: logits -> softmax -> weighted max aggregation --
// warp per dst node; lane owns dim pair (2l, 2l+1); We resident in registers
__global__ void __launch_bounds__(256, 3) k_gat(const float* __restrict__ edge_attr,
                                                const float* __restrict__ We,
                                                const float* __restrict__ ae,
                                                const float* __restrict__ bias,
                                                float* __restrict__ dout,
                                                int to_c1) {
    __shared__ float swetmp[DE];
    __shared__ u64 sWeA[DE / 2];   // paired (We@ae)
    __shared__ u64 sb2[32];
    float* __restrict__ out = to_c1 ? (float*)g_c1 : dout;
    int tid = threadIdx.x, lane = tid & 31, warp = tid >> 5;
    if (tid < DE) {
        float a = 0.f;
        #pragma unroll
        for (int d = 0; d < D; d++) a = fmaf(We[tid * D + d], ae[d], a);
        swetmp[tid] = a;
    }
    if (tid < 32) sb2[tid] = ((const u64*)bias)[tid];
    __syncthreads();
    if (tid < DE / 2) sWeA[tid] = pack2(swetmp[2 * tid], swetmp[2 * tid + 1]);
    __syncthreads();

    // register-resident We k-pairs for this lane's two dims
    int d0 = 2 * lane, d1 = d0 + 1;
    u64 wd0[8], wd1[8];
    #pragma unroll
    for (int j = 0; j < 8; j++) {
        wd0[j] = pack2(We[(2 * j) * D + d0], We[(2 * j + 1) * D + d0]);
        wd1[j] = pack2(We[(2 * j) * D + d1], We[(2 * j + 1) * D + d1]);
    }
    F2U bv; bv.u = sb2[lane];

    int gw = blockIdx.x * 8 + warp;
    int nw = gridDim.x * 8;

    for (int n = gw; n < NN; n += nw) {
        int beg = g_rowptr[n], end = g_rowptr[n + 1];
        float o0, o1;
        if (beg == end) {
            o0 = 0.f; o1 = 0.f;
        } else {
            float hdn = g_hd[n];
            // ---- pass 1: logits + segment max (lane-parallel over edges) ----
            float mmax = -CUDART_INF_F;
            for (int idx = beg + lane; idx < end; idx += 32) {
                int sr = g_srcc[idx];
                int e  = g_eid[idx];
                const float4* ea4 = (const float4*)(edge_attr + (size_t)e * DE);
                float4 A = ea4[0], B = ea4[1], C = ea4[2], Dd = ea4[3];
                u64 lacc = 0ull;
                lacc = fma2(pack2(A.x,  A.y),  sWeA[0], lacc);
                lacc = fma2(pack2(A.z,  A.w),  sWeA[1], lacc);
                lacc = fma2(pack2(B.x,  B.y),  sWeA[2], lacc);
                lacc = fma2(pack2(B.z,  B.w),  sWeA[3], lacc);
                lacc = fma2(pack2(C.x,  C.y),  sWeA[4], lacc);
                lacc = fma2(pack2(C.z,  C.w),  sWeA[5], lacc);
                lacc = fma2(pack2(Dd.x, Dd.y), sWeA[6], lacc);
                lacc = fma2(pack2(Dd.z, Dd.w), sWeA[7], lacc);
                F2U la; la.u = lacc;
                float l = g_hs[sr] + hdn + la.f.x + la.f.y;
                l = fmaxf(l, ATT_SLOPE * l);            // leaky_relu(l, 0.2)
                g_l[idx] = l;
                mmax = fmaxf(mmax, l);
            }
            #pragma unroll
            for (int o = 16; o; o >>= 1)
                mmax = fmaxf(mmax, __shfl_xor_sync(0xffffffffu, mmax, o));

            // ---- pass 1b: p = exp(l - m), s = sum p (each lane its own idx) --
            float s = 0.f;
            for (int idx = beg + lane; idx < end; idx += 32) {
                float p = __expf(g_l[idx] - mmax);      // arg <= 0
                g_l[idx] = p;
                s += p;
            }
            #pragma unroll
            for (int o = 16; o; o >>= 1)
                s += __shfl_xor_sync(0xffffffffu, s, o);
            __threadfence_block();
            __syncwarp();
            float inv = 1.0f / s;                       // s >= 1 always

            // ---- pass 2: max over edges of p*(h[src]+e), dims in lanes ------
            float a0 = -CUDART_INF_F, a1 = -CUDART_INF_F;
            for (int idx = beg; idx < end; idx++) {
                int e   = g_eid[idx];
                int sr  = g_srcc[idx];
                float p = g_l[idx];
                F2U hu; hu.f = g_h[sr * 32 + lane];
                const float4* ea4 = (const float4*)(edge_attr + (size_t)e * DE);
                float4 A = ea4[0], B = ea4[1], C = ea4[2], Dd = ea4[3];
                u64 p0 = pack2(A.x,  A.y);
                u64 p1 = pack2(A.z,  A.w);
                u64 p2 = pack2(B.x,  B.y);
                u64 p3 = pack2(B.z,  B.w);
                u64 p4 = pack2(C.x,  C.y);
                u64 p5 = pack2(C.z,  C.w);
                u64 p6 = pack2(Dd.x, Dd.y);
                u64 p7 = pack2(Dd.z, Dd.w);
                u64 e0 = 0ull, e1 = 0ull;
                e0 = fma2(p0, wd0[0], e0);  e1 = fma2(p0, wd1[0], e1);
                e0 = fma2(p1, wd0[1], e0);  e1 = fma2(p1, wd1[1], e1);
                e0 = fma2(p2, wd0[2], e0);  e1 = fma2(p2, wd1[2], e1);
                e0 = fma2(p3, wd0[3], e0);  e1 = fma2(p3, wd1[3], e1);
                e0 = fma2(p4, wd0[4], e0);  e1 = fma2(p4, wd1[4], e1);
                e0 = fma2(p5, wd0[5], e0);  e1 = fma2(p5, wd1[5], e1);
                e0 = fma2(p6, wd0[6], e0);  e1 = fma2(p6, wd1[6], e1);
                e0 = fma2(p7, wd0[7], e0);  e1 = fma2(p7, wd1[7], e1);
                F2U E0; E0.u = e0;
                F2U E1; E1.u = e1;
                float v0 = hu.f.x + (E0.f.x + E0.f.y);
                float v1 = hu.f.y + (E1.f.x + E1.f.y);
                a0 = fmaxf(a0, p * v0);
                a1 = fmaxf(a1, p * v1);
            }
            o0 = a0 * inv;
            o1 = a1 * inv;
        }
        o0 += bv.f.x;
        o1 += bv.f.y;
        o0 = fmaxf(o0, ACT_SLOPE * o0);                 // leaky_relu(., 0.01)
        o1 = fmaxf(o1, ACT_SLOPE * o1);
        ((float2*)out)[n * 32 + lane] = make_float2(o0, o1);
    }
}

// ---------------- launch -----------------------------------------------------
extern "C" void kernel_launch(void* const* d_in, const int* in_sizes, int n_in,
                              void* d_out, int out_size) {
    const float* X     = (const float*)d_in[0];
    const int*   ei    = (const int*)  d_in[1];
    const float* eattr = (const float*)d_in[2];
    const float* W1  = (const float*)d_in[3];
    const float* We1 = (const float*)d_in[4];
    const float* as1 = (const float*)d_in[5];
    const float* ad1 = (const float*)d_in[6];
    const float* ae1 = (const float*)d_in[7];
    const float* b1  = (const float*)d_in[8];
    const float* W2  = (const float*)d_in[9];
    const float* We2 = (const float*)d_in[10];
    const float* as2 = (const float*)d_in[11];
    const float* ad2 = (const float*)d_in[12];
    const float* ae2 = (const float*)d_in[13];
    const float* b2  = (const float*)d_in[14];

    const int* srcp = ei;
    const int* dstp = ei + EE;
    float* out = (float*)d_out;

    const int E4B = (EE / 4 + 255) / 256;        // 1563
    const int NB  = (NN + 255) / 256;            // 196
    const int SB  = (NN + 1023) / 1024;          // 49
    const int FB  = 296;                         // k_feat blocks
    const int GB  = 444;                         // k_gat blocks (3/SM)

    // CSR build (once per launch, shared by both layers)
    k_zero_deg<<<NB, 256>>>();
    k_hist<<<E4B, 256>>>(dstp);
    k_scan1<<<SB, 1024>>>();
    k_scan2<<<NB, 256>>>();
    k_scatter<<<E4B, 256>>>(srcp, dstp);

    // layer 1
    k_feat<<<FB, 256>>>(X, W1, as1, ad1, /*use_c1=*/0);
    k_gat <<<GB, 256>>>(eattr, We1, ae1, b1, out, /*to_c1=*/1);

    // layer 2
    k_feat<<<FB, 256>>>(nullptr, W2, as2, ad2, /*use_c1=*/1);
    k_gat <<<GB, 256>>>(eattr, We2, ae2, b2, out, /*to_c1=*/0);
}